// round 5
// baseline (speedup 1.0000x reference)
#include <cuda_runtime.h>
#include <cuda_fp16.h>
#include <cstdint>
#include <cstddef>

#define BROWS 32768
#define DIN   256
#define UNITS 512

static constexpr float DT  = 1.0f / 6.0f;
static constexpr float DT2 = DT * 0.5f;
static constexpr float DT3 = DT / 3.0f;
static constexpr float DT6 = DT / 6.0f;

// ------------------------------------------------------------------ scratch
__device__ alignas(16) float  g_XKb[(size_t)BROWS * UNITS];
__device__ alignas(16) float  g_S  [(size_t)BROWS * UNITS];
__device__ alignas(16) __half g_H0h[(size_t)BROWS * UNITS];
__device__ alignas(16) __half g_H0l[(size_t)BROWS * UNITS];
__device__ alignas(16) __half g_HAh[(size_t)BROWS * UNITS];
__device__ alignas(16) __half g_HAl[(size_t)BROWS * UNITS];
__device__ alignas(16) __half g_HBh[(size_t)BROWS * UNITS];
__device__ alignas(16) __half g_HBl[(size_t)BROWS * UNITS];
__device__ alignas(16) __half g_Xh [(size_t)BROWS * DIN];
__device__ alignas(16) __half g_Xl [(size_t)BROWS * DIN];
__device__ alignas(16) __half g_Rth[UNITS * UNITS];
__device__ alignas(16) __half g_Rtl[UNITS * UNITS];
__device__ alignas(16) __half g_Kth[UNITS * DIN];
__device__ alignas(16) __half g_Ktl[UNITS * DIN];

// ------------------------------------------------------------------ helpers
__device__ __forceinline__ uint32_t smem_u32(const void* p) {
    uint32_t a;
    asm("{ .reg .u64 t; cvta.to.shared.u64 t, %1; cvt.u32.u64 %0, t; }" : "=r"(a) : "l"(p));
    return a;
}

__device__ __forceinline__ void cp_async16(uint32_t saddr, const void* gaddr) {
    asm volatile("cp.async.cg.shared.global [%0], [%1], 16;" :: "r"(saddr), "l"(gaddr));
}
#define CP_COMMIT() asm volatile("cp.async.commit_group;" ::: "memory")
#define CP_WAIT(n)  asm volatile("cp.async.wait_group %0;" :: "n"(n) : "memory")

__device__ __forceinline__ void ldsm_x4(uint32_t addr, uint32_t& r0, uint32_t& r1,
                                        uint32_t& r2, uint32_t& r3) {
    asm volatile("ldmatrix.sync.aligned.m8n8.x4.shared.b16 {%0,%1,%2,%3}, [%4];"
                 : "=r"(r0), "=r"(r1), "=r"(r2), "=r"(r3) : "r"(addr));
}

__device__ __forceinline__ void mma16816(float* c, const uint32_t* a,
                                         uint32_t b0, uint32_t b1) {
    asm volatile("mma.sync.aligned.m16n8k16.row.col.f32.f16.f16.f32 "
                 "{%0,%1,%2,%3}, {%4,%5,%6,%7}, {%8,%9}, {%0,%1,%2,%3};"
                 : "+f"(c[0]), "+f"(c[1]), "+f"(c[2]), "+f"(c[3])
                 : "r"(a[0]), "r"(a[1]), "r"(a[2]), "r"(a[3]), "r"(b0), "r"(b1));
}

__device__ __forceinline__ float tanh_fast(float x) {
    const float e = __expf(2.0f * x);
    return 1.0f - 2.0f / (e + 1.0f);
}

__device__ __forceinline__ void hsplit2(__half* ph, __half* pl, float v0, float v1) {
    const __half h0 = __float2half(v0);
    const __half h1 = __float2half(v1);
    const __half l0 = __float2half(v0 - __half2float(h0));
    const __half l1 = __float2half(v1 - __half2float(h1));
    __half2 hh; hh.x = h0; hh.y = h1;
    __half2 ll; ll.x = l0; ll.y = l1;
    *reinterpret_cast<__half2*>(ph) = hh;
    *reinterpret_cast<__half2*>(pl) = ll;
}

// ------------------------------------------------------------------ smem map (dynamic)
static constexpr uint32_t TILE_BYTES = 128 * 128;         // 128 rows x 128B (64 halfs)
static constexpr uint32_t OFF_A0  = 0;
static constexpr uint32_t OFF_A1  = OFF_A0 + TILE_BYTES;  // 16384
static constexpr uint32_t OFF_B0  = OFF_A1 + TILE_BYTES;  // 32768
static constexpr uint32_t OFF_B1  = OFF_B0 + TILE_BYTES;  // 49152
static constexpr uint32_t OFF_SCL = OFF_B1 + TILE_BYTES;  // 65536
static constexpr uint32_t SMEM_BYTES = OFF_SCL + 512 + 16;

// ------------------------------------------------------------------ main GEMM + RK4 epilogue
// MODE 0: XKb = x@K + bias (KSEG=256).  MODE 1..4: RK4 stages (KSEG=512).
template <int MODE, int KSEG, bool LAST>
__global__ void __launch_bounds__(256, 2)
ctrnn_gemm(const float* __restrict__ sb, float* __restrict__ outp) {
    extern __shared__ char smem[];
    const uint32_t sbase = smem_u32(smem);
    const int tid  = threadIdx.x;
    const int lane = tid & 31;
    const int wid  = tid >> 5;
    const int warpM = (wid & 3) * 32;        // 4 warps along M
    const int warpN = (wid >> 2) * 64;       // 2 warps along N
    const int rowBase = blockIdx.x * 128;
    const int nBase   = blockIdx.y * 128;

    constexpr int CHPS = KSEG / 64;
    constexpr int NCH  = 3 * CHPS;

    const __half *Ah, *Al, *Bh, *Bl;
    if constexpr (MODE == 0)      { Ah = g_Xh;  Al = g_Xl;  Bh = g_Kth; Bl = g_Ktl; }
    else if constexpr (MODE == 1) { Ah = g_H0h; Al = g_H0l; Bh = g_Rth; Bl = g_Rtl; }
    else if constexpr (MODE == 2) { Ah = g_HAh; Al = g_HAl; Bh = g_Rth; Bl = g_Rtl; }
    else if constexpr (MODE == 3) { Ah = g_HBh; Al = g_HBl; Bh = g_Rth; Bl = g_Rtl; }
    else                          { Ah = g_HAh; Al = g_HAl; Bh = g_Rth; Bl = g_Rtl; }

    __half *nxh = nullptr, *nxl = nullptr;
    if constexpr (MODE == 1)               { nxh = g_HAh; nxl = g_HAl; }
    else if constexpr (MODE == 2)          { nxh = g_HBh; nxl = g_HBl; }
    else if constexpr (MODE == 3)          { nxh = g_HAh; nxl = g_HAl; }
    else if constexpr (MODE == 4 && !LAST) { nxh = g_H0h; nxl = g_H0l; }

    if (tid < 128)
        reinterpret_cast<float*>(smem + OFF_SCL)[tid] = sb[nBase + tid];

    const __half* Aseg[3] = {Ah, Al, Ah};
    const __half* Bseg[3] = {Bh, Bh, Bl};

    // slot mapping for cp.async: 1024 slots per tile (128 rows x 8 col16)
    const int srow = tid >> 3;            // +64 per iter (i*32 rows per 256 thr... see loop)
    const int scol = tid & 7;

    auto load_chunk = [&](int c, int buf) {
        const int seg = c / CHPS;
        const int kof = (c % CHPS) * 64;
        const __half* As = Aseg[seg];
        const __half* Bs = Bseg[seg];
        const uint32_t aOff = buf ? OFF_A1 : OFF_A0;
        const uint32_t bOff = buf ? OFF_B1 : OFF_B0;
#pragma unroll
        for (int i = 0; i < 4; ++i) {
            const int r = srow + i * 32;
            uint32_t off = (uint32_t)(r * 128 + ((scol ^ (r & 7)) << 4));
            cp_async16(sbase + aOff + off,
                       As + (size_t)(rowBase + r) * KSEG + kof + scol * 8);
        }
#pragma unroll
        for (int i = 0; i < 4; ++i) {
            const int r = srow + i * 32;
            uint32_t off = (uint32_t)(r * 128 + ((scol ^ (r & 7)) << 4));
            cp_async16(sbase + bOff + off,
                       Bs + (size_t)(nBase + r) * KSEG + kof + scol * 8);
        }
        CP_COMMIT();
    };

    float acc[2][8][4];
#pragma unroll
    for (int mf = 0; mf < 2; ++mf)
#pragma unroll
        for (int nf = 0; nf < 8; ++nf)
#pragma unroll
            for (int i = 0; i < 4; ++i) acc[mf][nf][i] = 0.0f;

    load_chunk(0, 0);

    for (int c = 0; c < NCH; ++c) {
        if (c + 1 < NCH) load_chunk(c + 1, (c + 1) & 1);
        if (c + 1 < NCH) { CP_WAIT(1); } else { CP_WAIT(0); }
        __syncthreads();

        const uint32_t aBase = sbase + ((c & 1) ? OFF_A1 : OFF_A0);
        const uint32_t bBase = sbase + ((c & 1) ? OFF_B1 : OFF_B0);
#pragma unroll
        for (int q = 0; q < 4; ++q) {
            uint32_t a[2][4];
#pragma unroll
            for (int mf = 0; mf < 2; ++mf) {
                const int row = warpM + mf * 16 + ((lane >> 3) & 1) * 8 + (lane & 7);
                const int c16 = q * 2 + (lane >> 4);
                const uint32_t addr = aBase + row * 128 + (((c16 ^ (row & 7)) & 7) << 4);
                ldsm_x4(addr, a[mf][0], a[mf][1], a[mf][2], a[mf][3]);
            }
#pragma unroll
            for (int g = 0; g < 4; ++g) {
                uint32_t b0, b1, b2, b3;
                const int row = warpN + g * 16 + ((lane >> 3) & 1) * 8 + (lane & 7);
                const int c16 = q * 2 + (lane >> 4);
                const uint32_t addr = bBase + row * 128 + (((c16 ^ (row & 7)) & 7) << 4);
                ldsm_x4(addr, b0, b1, b2, b3);
#pragma unroll
                for (int mf = 0; mf < 2; ++mf) {
                    mma16816(acc[mf][2 * g],     a[mf], b0, b2);
                    mma16816(acc[mf][2 * g + 1], a[mf], b1, b3);
                }
            }
        }
        __syncthreads();
    }

    // ---------------- RK4 epilogue ----------------
    const float* scl = reinterpret_cast<const float*>(smem + OFF_SCL);

#pragma unroll
    for (int mf = 0; mf < 2; ++mf) {
#pragma unroll
        for (int nf = 0; nf < 8; ++nf) {
#pragma unroll
            for (int half_ = 0; half_ < 2; ++half_) {
                const int row = rowBase + warpM + mf * 16 + (lane >> 2) + half_ * 8;
                const int lc  = warpN + nf * 8 + (lane & 3) * 2;   // local col 0..127
                const int col = nBase + lc;
                const float c0 = acc[mf][nf][half_ * 2 + 0];
                const float c1 = acc[mf][nf][half_ * 2 + 1];
                const size_t eb = (size_t)row * UNITS + col;

                if constexpr (MODE == 0) {
                    float2 o;
                    o.x = c0 + scl[lc];
                    o.y = c1 + scl[lc + 1];
                    *reinterpret_cast<float2*>(g_XKb + eb) = o;
                } else {
                    const float2 xk = *reinterpret_cast<const float2*>(g_XKb + eb);
                    const __half2 ah = *reinterpret_cast<const __half2*>(Ah + eb);
                    const __half2 al = *reinterpret_cast<const __half2*>(Al + eb);
                    const float hs0 = __half2float(ah.x) + __half2float(al.x);
                    const float hs1 = __half2float(ah.y) + __half2float(al.y);
                    const float k0 = scl[lc]     * tanh_fast(c0 + xk.x) - hs0;
                    const float k1 = scl[lc + 1] * tanh_fast(c1 + xk.y) - hs1;

                    if constexpr (MODE == 1) {
                        hsplit2(nxh + eb, nxl + eb, hs0 + DT2 * k0, hs1 + DT2 * k1);
                        float2 sv; sv.x = hs0 + DT6 * k0; sv.y = hs1 + DT6 * k1;
                        *reinterpret_cast<float2*>(g_S + eb) = sv;
                    } else if constexpr (MODE == 2 || MODE == 3) {
                        const __half2 h0a = *reinterpret_cast<const __half2*>(g_H0h + eb);
                        const __half2 h0b = *reinterpret_cast<const __half2*>(g_H0l + eb);
                        const float h00 = __half2float(h0a.x) + __half2float(h0b.x);
                        const float h01 = __half2float(h0a.y) + __half2float(h0b.y);
                        const float2 s = *reinterpret_cast<const float2*>(g_S + eb);
                        constexpr float HC = (MODE == 2) ? DT2 : DT;
                        hsplit2(nxh + eb, nxl + eb, h00 + HC * k0, h01 + HC * k1);
                        float2 sn; sn.x = s.x + DT3 * k0; sn.y = s.y + DT3 * k1;
                        *reinterpret_cast<float2*>(g_S + eb) = sn;
                    } else {  // MODE 4
                        const float2 s = *reinterpret_cast<const float2*>(g_S + eb);
                        const float f0 = s.x + DT6 * k0;
                        const float f1 = s.y + DT6 * k1;
                        if constexpr (LAST) {
                            float2 o; o.x = f0; o.y = f1;
                            *reinterpret_cast<float2*>(outp + eb) = o;
                        } else {
                            hsplit2(nxh + eb, nxl + eb, f0, f1);
                        }
                    }
                }
            }
        }
    }
}

// ------------------------------------------------------------------ prep kernels
__global__ void split_kernel(const float* __restrict__ src,
                             __half* __restrict__ hi, __half* __restrict__ lo, int n4) {
    const int i = blockIdx.x * blockDim.x + threadIdx.x;
    if (i >= n4) return;
    const float4 v = reinterpret_cast<const float4*>(src)[i];
    hsplit2(hi + (size_t)i * 4,     lo + (size_t)i * 4,     v.x, v.y);
    hsplit2(hi + (size_t)i * 4 + 2, lo + (size_t)i * 4 + 2, v.z, v.w);
}

__global__ void trans_split_kernel(const float* __restrict__ W,
                                   __half* __restrict__ Th, __half* __restrict__ Tl,
                                   int K, int N) {
    const int idx = blockIdx.x * blockDim.x + threadIdx.x;
    if (idx >= K * N) return;
    const int k = idx / N, n = idx % N;
    const float v = W[idx];
    const __half h = __float2half(v);
    const __half l = __float2half(v - __half2float(h));
    Th[(size_t)n * K + k] = h;
    Tl[(size_t)n * K + k] = l;
}

// ------------------------------------------------------------------ launch
extern "C" void kernel_launch(void* const* d_in, const int* in_sizes, int n_in,
                              void* d_out, int out_size) {
    const float* x     = (const float*)d_in[0];
    const float* h     = (const float*)d_in[1];
    const float* Km    = (const float*)d_in[2];
    const float* Rm    = (const float*)d_in[3];
    const float* bias  = (const float*)d_in[4];
    const float* scale = (const float*)d_in[5];
    float* out = (float*)d_out;

    cudaFuncSetAttribute(ctrnn_gemm<0, 256, false>, cudaFuncAttributeMaxDynamicSharedMemorySize, SMEM_BYTES);
    cudaFuncSetAttribute(ctrnn_gemm<1, 512, false>, cudaFuncAttributeMaxDynamicSharedMemorySize, SMEM_BYTES);
    cudaFuncSetAttribute(ctrnn_gemm<2, 512, false>, cudaFuncAttributeMaxDynamicSharedMemorySize, SMEM_BYTES);
    cudaFuncSetAttribute(ctrnn_gemm<3, 512, false>, cudaFuncAttributeMaxDynamicSharedMemorySize, SMEM_BYTES);
    cudaFuncSetAttribute(ctrnn_gemm<4, 512, false>, cudaFuncAttributeMaxDynamicSharedMemorySize, SMEM_BYTES);
    cudaFuncSetAttribute(ctrnn_gemm<4, 512, true>,  cudaFuncAttributeMaxDynamicSharedMemorySize, SMEM_BYTES);

    __half *h0h, *h0l, *xh, *xl, *rth, *rtl, *kth, *ktl;
    cudaGetSymbolAddress((void**)&h0h, g_H0h);
    cudaGetSymbolAddress((void**)&h0l, g_H0l);
    cudaGetSymbolAddress((void**)&xh,  g_Xh);
    cudaGetSymbolAddress((void**)&xl,  g_Xl);
    cudaGetSymbolAddress((void**)&rth, g_Rth);
    cudaGetSymbolAddress((void**)&rtl, g_Rtl);
    cudaGetSymbolAddress((void**)&kth, g_Kth);
    cudaGetSymbolAddress((void**)&ktl, g_Ktl);

    split_kernel<<<(BROWS * UNITS / 4) / 256, 256>>>(h, h0h, h0l, BROWS * UNITS / 4);
    split_kernel<<<(BROWS * DIN / 4) / 256, 256>>>(x, xh, xl, BROWS * DIN / 4);
    trans_split_kernel<<<(UNITS * UNITS) / 256, 256>>>(Rm, rth, rtl, UNITS, UNITS);
    trans_split_kernel<<<(DIN * UNITS) / 256, 256>>>(Km, kth, ktl, DIN, UNITS);

    const dim3 gg(BROWS / 128, UNITS / 128);
    ctrnn_gemm<0, 256, false><<<gg, 256, SMEM_BYTES>>>(bias, nullptr);

    for (int u = 0; u < 6; ++u) {
        ctrnn_gemm<1, 512, false><<<gg, 256, SMEM_BYTES>>>(scale, nullptr);
        ctrnn_gemm<2, 512, false><<<gg, 256, SMEM_BYTES>>>(scale, nullptr);
        ctrnn_gemm<3, 512, false><<<gg, 256, SMEM_BYTES>>>(scale, nullptr);
        if (u == 5) ctrnn_gemm<4, 512, true><<<gg, 256, SMEM_BYTES>>>(scale, out);
        else        ctrnn_gemm<4, 512, false><<<gg, 256, SMEM_BYTES>>>(scale, nullptr);
    }
}

// round 6
// speedup vs baseline: 1.0016x; 1.0016x over previous
#include <cuda_runtime.h>
#include <cuda_fp16.h>
#include <cstdint>
#include <cstddef>

#define BROWS 32768
#define DIN   256
#define UNITS 512

static constexpr float DT  = 1.0f / 6.0f;
static constexpr float DT2 = DT * 0.5f;
static constexpr float DT3 = DT / 3.0f;
static constexpr float DT6 = DT / 6.0f;

// ------------------------------------------------------------------ scratch
__device__ alignas(16) float  g_XKb[(size_t)BROWS * UNITS];
__device__ alignas(16) float  g_S  [(size_t)BROWS * UNITS];
__device__ alignas(16) __half g_H0h[(size_t)BROWS * UNITS];
__device__ alignas(16) __half g_H0l[(size_t)BROWS * UNITS];
__device__ alignas(16) __half g_HAh[(size_t)BROWS * UNITS];
__device__ alignas(16) __half g_HAl[(size_t)BROWS * UNITS];
__device__ alignas(16) __half g_HBh[(size_t)BROWS * UNITS];
__device__ alignas(16) __half g_HBl[(size_t)BROWS * UNITS];
__device__ alignas(16) __half g_Xh [(size_t)BROWS * DIN];
__device__ alignas(16) __half g_Xl [(size_t)BROWS * DIN];
__device__ alignas(16) __half g_Rth[UNITS * UNITS];
__device__ alignas(16) __half g_Rtl[UNITS * UNITS];
__device__ alignas(16) __half g_Kth[UNITS * DIN];
__device__ alignas(16) __half g_Ktl[UNITS * DIN];

// ------------------------------------------------------------------ helpers
__device__ __forceinline__ uint32_t smem_u32(const void* p) {
    uint32_t a;
    asm("{ .reg .u64 t; cvta.to.shared.u64 t, %1; cvt.u32.u64 %0, t; }" : "=r"(a) : "l"(p));
    return a;
}

__device__ __forceinline__ void cp_async16(uint32_t saddr, const void* gaddr) {
    asm volatile("cp.async.cg.shared.global [%0], [%1], 16;" :: "r"(saddr), "l"(gaddr));
}
#define CP_COMMIT() asm volatile("cp.async.commit_group;" ::: "memory")
#define CP_WAIT(n)  asm volatile("cp.async.wait_group %0;" :: "n"(n) : "memory")

__device__ __forceinline__ void ldsm_x4(uint32_t addr, uint32_t& r0, uint32_t& r1,
                                        uint32_t& r2, uint32_t& r3) {
    asm volatile("ldmatrix.sync.aligned.m8n8.x4.shared.b16 {%0,%1,%2,%3}, [%4];"
                 : "=r"(r0), "=r"(r1), "=r"(r2), "=r"(r3) : "r"(addr));
}

__device__ __forceinline__ void mma16816(float* c, const uint32_t* a,
                                         uint32_t b0, uint32_t b1) {
    asm volatile("mma.sync.aligned.m16n8k16.row.col.f32.f16.f16.f32 "
                 "{%0,%1,%2,%3}, {%4,%5,%6,%7}, {%8,%9}, {%0,%1,%2,%3};"
                 : "+f"(c[0]), "+f"(c[1]), "+f"(c[2]), "+f"(c[3])
                 : "r"(a[0]), "r"(a[1]), "r"(a[2]), "r"(a[3]), "r"(b0), "r"(b1));
}

__device__ __forceinline__ float tanh_fast(float x) {
    const float e = __expf(2.0f * x);
    return 1.0f - 2.0f / (e + 1.0f);
}

__device__ __forceinline__ void hsplit2(__half* ph, __half* pl, float v0, float v1) {
    const __half h0 = __float2half(v0);
    const __half h1 = __float2half(v1);
    const __half l0 = __float2half(v0 - __half2float(h0));
    const __half l1 = __float2half(v1 - __half2float(h1));
    __half2 hh; hh.x = h0; hh.y = h1;
    __half2 ll; ll.x = l0; ll.y = l1;
    *reinterpret_cast<__half2*>(ph) = hh;
    *reinterpret_cast<__half2*>(pl) = ll;
}

// ------------------------------------------------------------------ smem map (dynamic)
static constexpr uint32_t TILE_BYTES = 128 * 128;         // 128 rows x 128B (64 halfs)
static constexpr uint32_t OFF_A0  = 0;
static constexpr uint32_t OFF_A1  = OFF_A0 + TILE_BYTES;  // 16384
static constexpr uint32_t OFF_B0  = OFF_A1 + TILE_BYTES;  // 32768
static constexpr uint32_t OFF_B1  = OFF_B0 + TILE_BYTES;  // 49152
static constexpr uint32_t OFF_SCL = OFF_B1 + TILE_BYTES;  // 65536
static constexpr uint32_t SMEM_BYTES = OFF_SCL + 512 + 16;

// ------------------------------------------------------------------ main GEMM + RK4 epilogue
// MODE 0: XKb = x@K + bias (KSEG=256).  MODE 1..4: RK4 stages (KSEG=512).
template <int MODE, int KSEG, bool LAST>
__global__ void __launch_bounds__(256, 2)
ctrnn_gemm(const float* __restrict__ sb, float* __restrict__ outp) {
    extern __shared__ char smem[];
    const uint32_t sbase = smem_u32(smem);
    const int tid  = threadIdx.x;
    const int lane = tid & 31;
    const int wid  = tid >> 5;
    const int warpM = (wid & 3) * 32;        // 4 warps along M
    const int warpN = (wid >> 2) * 64;       // 2 warps along N
    const int rowBase = blockIdx.x * 128;
    const int nBase   = blockIdx.y * 128;

    constexpr int CHPS = KSEG / 64;
    constexpr int NCH  = 3 * CHPS;

    const __half *Ah, *Al, *Bh, *Bl;
    if constexpr (MODE == 0)      { Ah = g_Xh;  Al = g_Xl;  Bh = g_Kth; Bl = g_Ktl; }
    else if constexpr (MODE == 1) { Ah = g_H0h; Al = g_H0l; Bh = g_Rth; Bl = g_Rtl; }
    else if constexpr (MODE == 2) { Ah = g_HAh; Al = g_HAl; Bh = g_Rth; Bl = g_Rtl; }
    else if constexpr (MODE == 3) { Ah = g_HBh; Al = g_HBl; Bh = g_Rth; Bl = g_Rtl; }
    else                          { Ah = g_HAh; Al = g_HAl; Bh = g_Rth; Bl = g_Rtl; }

    __half *nxh = nullptr, *nxl = nullptr;
    if constexpr (MODE == 1)               { nxh = g_HAh; nxl = g_HAl; }
    else if constexpr (MODE == 2)          { nxh = g_HBh; nxl = g_HBl; }
    else if constexpr (MODE == 3)          { nxh = g_HAh; nxl = g_HAl; }
    else if constexpr (MODE == 4 && !LAST) { nxh = g_H0h; nxl = g_H0l; }

    if (tid < 128)
        reinterpret_cast<float*>(smem + OFF_SCL)[tid] = sb[nBase + tid];

    const __half* Aseg[3] = {Ah, Al, Ah};
    const __half* Bseg[3] = {Bh, Bh, Bl};

    // slot mapping for cp.async: 1024 slots per tile (128 rows x 8 col16)
    const int srow = tid >> 3;
    const int scol = tid & 7;

    auto load_chunk = [&](int c, int buf) {
        const int seg = c / CHPS;
        const int kof = (c % CHPS) * 64;
        const __half* As = Aseg[seg];
        const __half* Bs = Bseg[seg];
        const uint32_t aOff = buf ? OFF_A1 : OFF_A0;
        const uint32_t bOff = buf ? OFF_B1 : OFF_B0;
#pragma unroll
        for (int i = 0; i < 4; ++i) {
            const int r = srow + i * 32;
            uint32_t off = (uint32_t)(r * 128 + ((scol ^ (r & 7)) << 4));
            cp_async16(sbase + aOff + off,
                       As + (size_t)(rowBase + r) * KSEG + kof + scol * 8);
        }
#pragma unroll
        for (int i = 0; i < 4; ++i) {
            const int r = srow + i * 32;
            uint32_t off = (uint32_t)(r * 128 + ((scol ^ (r & 7)) << 4));
            cp_async16(sbase + bOff + off,
                       Bs + (size_t)(nBase + r) * KSEG + kof + scol * 8);
        }
        CP_COMMIT();
    };

    float acc[2][8][4];
#pragma unroll
    for (int mf = 0; mf < 2; ++mf)
#pragma unroll
        for (int nf = 0; nf < 8; ++nf)
#pragma unroll
            for (int i = 0; i < 4; ++i) acc[mf][nf][i] = 0.0f;

    // -------- canonical 2-stage pipeline: ONE barrier per chunk --------
    // iter c:  wait L(c) -> barrier -> issue L(c+1) (overlaps MMA) -> MMA(c)
    // L(c+1) writes buf (c+1)&1 whose last readers (MMA(c-1)) finished
    // before this iteration's barrier, so a single barrier is sufficient.
    load_chunk(0, 0);

    for (int c = 0; c < NCH; ++c) {
        CP_WAIT(0);
        __syncthreads();
        if (c + 1 < NCH) load_chunk(c + 1, (c + 1) & 1);

        const uint32_t aBase = sbase + ((c & 1) ? OFF_A1 : OFF_A0);
        const uint32_t bBase = sbase + ((c & 1) ? OFF_B1 : OFF_B0);
#pragma unroll
        for (int q = 0; q < 4; ++q) {
            uint32_t a[2][4];
#pragma unroll
            for (int mf = 0; mf < 2; ++mf) {
                const int row = warpM + mf * 16 + ((lane >> 3) & 1) * 8 + (lane & 7);
                const int c16 = q * 2 + (lane >> 4);
                const uint32_t addr = aBase + row * 128 + (((c16 ^ (row & 7)) & 7) << 4);
                ldsm_x4(addr, a[mf][0], a[mf][1], a[mf][2], a[mf][3]);
            }
#pragma unroll
            for (int g = 0; g < 4; ++g) {
                uint32_t b0, b1, b2, b3;
                const int row = warpN + g * 16 + ((lane >> 3) & 1) * 8 + (lane & 7);
                const int c16 = q * 2 + (lane >> 4);
                const uint32_t addr = bBase + row * 128 + (((c16 ^ (row & 7)) & 7) << 4);
                ldsm_x4(addr, b0, b1, b2, b3);
#pragma unroll
                for (int mf = 0; mf < 2; ++mf) {
                    mma16816(acc[mf][2 * g],     a[mf], b0, b2);
                    mma16816(acc[mf][2 * g + 1], a[mf], b1, b3);
                }
            }
        }
    }

    // ---------------- RK4 epilogue ----------------
    const float* scl = reinterpret_cast<const float*>(smem + OFF_SCL);

#pragma unroll
    for (int mf = 0; mf < 2; ++mf) {
#pragma unroll
        for (int nf = 0; nf < 8; ++nf) {
#pragma unroll
            for (int half_ = 0; half_ < 2; ++half_) {
                const int row = rowBase + warpM + mf * 16 + (lane >> 2) + half_ * 8;
                const int lc  = warpN + nf * 8 + (lane & 3) * 2;   // local col 0..127
                const int col = nBase + lc;
                const float c0 = acc[mf][nf][half_ * 2 + 0];
                const float c1 = acc[mf][nf][half_ * 2 + 1];
                const size_t eb = (size_t)row * UNITS + col;

                if constexpr (MODE == 0) {
                    float2 o;
                    o.x = c0 + scl[lc];
                    o.y = c1 + scl[lc + 1];
                    *reinterpret_cast<float2*>(g_XKb + eb) = o;
                } else {
                    const float2 xk = *reinterpret_cast<const float2*>(g_XKb + eb);
                    const __half2 ah = *reinterpret_cast<const __half2*>(Ah + eb);
                    const __half2 al = *reinterpret_cast<const __half2*>(Al + eb);
                    const float hs0 = __half2float(ah.x) + __half2float(al.x);
                    const float hs1 = __half2float(ah.y) + __half2float(al.y);
                    const float k0 = scl[lc]     * tanh_fast(c0 + xk.x) - hs0;
                    const float k1 = scl[lc + 1] * tanh_fast(c1 + xk.y) - hs1;

                    if constexpr (MODE == 1) {
                        hsplit2(nxh + eb, nxl + eb, hs0 + DT2 * k0, hs1 + DT2 * k1);
                        float2 sv; sv.x = hs0 + DT6 * k0; sv.y = hs1 + DT6 * k1;
                        *reinterpret_cast<float2*>(g_S + eb) = sv;
                    } else if constexpr (MODE == 2 || MODE == 3) {
                        const __half2 h0a = *reinterpret_cast<const __half2*>(g_H0h + eb);
                        const __half2 h0b = *reinterpret_cast<const __half2*>(g_H0l + eb);
                        const float h00 = __half2float(h0a.x) + __half2float(h0b.x);
                        const float h01 = __half2float(h0a.y) + __half2float(h0b.y);
                        const float2 s = *reinterpret_cast<const float2*>(g_S + eb);
                        constexpr float HC = (MODE == 2) ? DT2 : DT;
                        hsplit2(nxh + eb, nxl + eb, h00 + HC * k0, h01 + HC * k1);
                        float2 sn; sn.x = s.x + DT3 * k0; sn.y = s.y + DT3 * k1;
                        *reinterpret_cast<float2*>(g_S + eb) = sn;
                    } else {  // MODE 4
                        const float2 s = *reinterpret_cast<const float2*>(g_S + eb);
                        const float f0 = s.x + DT6 * k0;
                        const float f1 = s.y + DT6 * k1;
                        if constexpr (LAST) {
                            float2 o; o.x = f0; o.y = f1;
                            *reinterpret_cast<float2*>(outp + eb) = o;
                        } else {
                            hsplit2(nxh + eb, nxl + eb, f0, f1);
                        }
                    }
                }
            }
        }
    }
}

// ------------------------------------------------------------------ prep kernels
__global__ void split_kernel(const float* __restrict__ src,
                             __half* __restrict__ hi, __half* __restrict__ lo, int n4) {
    const int i = blockIdx.x * blockDim.x + threadIdx.x;
    if (i >= n4) return;
    const float4 v = reinterpret_cast<const float4*>(src)[i];
    hsplit2(hi + (size_t)i * 4,     lo + (size_t)i * 4,     v.x, v.y);
    hsplit2(hi + (size_t)i * 4 + 2, lo + (size_t)i * 4 + 2, v.z, v.w);
}

__global__ void trans_split_kernel(const float* __restrict__ W,
                                   __half* __restrict__ Th, __half* __restrict__ Tl,
                                   int K, int N) {
    const int idx = blockIdx.x * blockDim.x + threadIdx.x;
    if (idx >= K * N) return;
    const int k = idx / N, n = idx % N;
    const float v = W[idx];
    const __half h = __float2half(v);
    const __half l = __float2half(v - __half2float(h));
    Th[(size_t)n * K + k] = h;
    Tl[(size_t)n * K + k] = l;
}

// ------------------------------------------------------------------ launch
extern "C" void kernel_launch(void* const* d_in, const int* in_sizes, int n_in,
                              void* d_out, int out_size) {
    const float* x     = (const float*)d_in[0];
    const float* h     = (const float*)d_in[1];
    const float* Km    = (const float*)d_in[2];
    const float* Rm    = (const float*)d_in[3];
    const float* bias  = (const float*)d_in[4];
    const float* scale = (const float*)d_in[5];
    float* out = (float*)d_out;

    cudaFuncSetAttribute(ctrnn_gemm<0, 256, false>, cudaFuncAttributeMaxDynamicSharedMemorySize, SMEM_BYTES);
    cudaFuncSetAttribute(ctrnn_gemm<1, 512, false>, cudaFuncAttributeMaxDynamicSharedMemorySize, SMEM_BYTES);
    cudaFuncSetAttribute(ctrnn_gemm<2, 512, false>, cudaFuncAttributeMaxDynamicSharedMemorySize, SMEM_BYTES);
    cudaFuncSetAttribute(ctrnn_gemm<3, 512, false>, cudaFuncAttributeMaxDynamicSharedMemorySize, SMEM_BYTES);
    cudaFuncSetAttribute(ctrnn_gemm<4, 512, false>, cudaFuncAttributeMaxDynamicSharedMemorySize, SMEM_BYTES);
    cudaFuncSetAttribute(ctrnn_gemm<4, 512, true>,  cudaFuncAttributeMaxDynamicSharedMemorySize, SMEM_BYTES);

    __half *h0h, *h0l, *xh, *xl, *rth, *rtl, *kth, *ktl;
    cudaGetSymbolAddress((void**)&h0h, g_H0h);
    cudaGetSymbolAddress((void**)&h0l, g_H0l);
    cudaGetSymbolAddress((void**)&xh,  g_Xh);
    cudaGetSymbolAddress((void**)&xl,  g_Xl);
    cudaGetSymbolAddress((void**)&rth, g_Rth);
    cudaGetSymbolAddress((void**)&rtl, g_Rtl);
    cudaGetSymbolAddress((void**)&kth, g_Kth);
    cudaGetSymbolAddress((void**)&ktl, g_Ktl);

    split_kernel<<<(BROWS * UNITS / 4) / 256, 256>>>(h, h0h, h0l, BROWS * UNITS / 4);
    split_kernel<<<(BROWS * DIN / 4) / 256, 256>>>(x, xh, xl, BROWS * DIN / 4);
    trans_split_kernel<<<(UNITS * UNITS) / 256, 256>>>(Rm, rth, rtl, UNITS, UNITS);
    trans_split_kernel<<<(DIN * UNITS) / 256, 256>>>(Km, kth, ktl, DIN, UNITS);

    const dim3 gg(BROWS / 128, UNITS / 128);
    ctrnn_gemm<0, 256, false><<<gg, 256, SMEM_BYTES>>>(bias, nullptr);

    for (int u = 0; u < 6; ++u) {
        ctrnn_gemm<1, 512, false><<<gg, 256, SMEM_BYTES>>>(scale, nullptr);
        ctrnn_gemm<2, 512, false><<<gg, 256, SMEM_BYTES>>>(scale, nullptr);
        ctrnn_gemm<3, 512, false><<<gg, 256, SMEM_BYTES>>>(scale, nullptr);
        if (u == 5) ctrnn_gemm<4, 512, true><<<gg, 256, SMEM_BYTES>>>(scale, out);
        else        ctrnn_gemm<4, 512, false><<<gg, 256, SMEM_BYTES>>>(scale, nullptr);
    }
}

// round 7
// speedup vs baseline: 1.1970x; 1.1951x over previous
#include <cuda_runtime.h>
#include <cuda_fp16.h>
#include <cstdint>
#include <cstddef>

#define BROWS 32768
#define DIN   256
#define UNITS 512

static constexpr float DT  = 1.0f / 6.0f;
static constexpr float DT2 = DT * 0.5f;
static constexpr float DT3 = DT / 3.0f;
static constexpr float DT6 = DT / 6.0f;

// ------------------------------------------------------------------ scratch
__device__ alignas(16) float  g_XKb[(size_t)BROWS * UNITS];
__device__ alignas(16) float  g_S  [(size_t)BROWS * UNITS];
__device__ alignas(16) __half g_H0h[(size_t)BROWS * UNITS];
__device__ alignas(16) __half g_H0l[(size_t)BROWS * UNITS];
__device__ alignas(16) __half g_HAh[(size_t)BROWS * UNITS];
__device__ alignas(16) __half g_HAl[(size_t)BROWS * UNITS];
__device__ alignas(16) __half g_HBh[(size_t)BROWS * UNITS];
__device__ alignas(16) __half g_HBl[(size_t)BROWS * UNITS];
__device__ alignas(16) __half g_Xh [(size_t)BROWS * DIN];
__device__ alignas(16) __half g_Xl [(size_t)BROWS * DIN];
__device__ alignas(16) __half g_Rth[UNITS * UNITS];
__device__ alignas(16) __half g_Kth[UNITS * DIN];

// ------------------------------------------------------------------ helpers
__device__ __forceinline__ uint32_t smem_u32(const void* p) {
    uint32_t a;
    asm("{ .reg .u64 t; cvta.to.shared.u64 t, %1; cvt.u32.u64 %0, t; }" : "=r"(a) : "l"(p));
    return a;
}

__device__ __forceinline__ void cp_async16(uint32_t saddr, const void* gaddr) {
    asm volatile("cp.async.cg.shared.global [%0], [%1], 16;" :: "r"(saddr), "l"(gaddr));
}
#define CP_COMMIT() asm volatile("cp.async.commit_group;" ::: "memory")
#define CP_WAIT(n)  asm volatile("cp.async.wait_group %0;" :: "n"(n) : "memory")

__device__ __forceinline__ void ldsm_x4(uint32_t addr, uint32_t& r0, uint32_t& r1,
                                        uint32_t& r2, uint32_t& r3) {
    asm volatile("ldmatrix.sync.aligned.m8n8.x4.shared.b16 {%0,%1,%2,%3}, [%4];"
                 : "=r"(r0), "=r"(r1), "=r"(r2), "=r"(r3) : "r"(addr));
}

__device__ __forceinline__ void mma16816(float* c, const uint32_t* a,
                                         uint32_t b0, uint32_t b1) {
    asm volatile("mma.sync.aligned.m16n8k16.row.col.f32.f16.f16.f32 "
                 "{%0,%1,%2,%3}, {%4,%5,%6,%7}, {%8,%9}, {%0,%1,%2,%3};"
                 : "+f"(c[0]), "+f"(c[1]), "+f"(c[2]), "+f"(c[3])
                 : "r"(a[0]), "r"(a[1]), "r"(a[2]), "r"(a[3]), "r"(b0), "r"(b1));
}

__device__ __forceinline__ float tanh_fast(float x) {
    const float e = __expf(2.0f * x);
    return 1.0f - 2.0f / (e + 1.0f);
}

__device__ __forceinline__ void hsplit2(__half* ph, __half* pl, float v0, float v1) {
    const __half h0 = __float2half(v0);
    const __half h1 = __float2half(v1);
    const __half l0 = __float2half(v0 - __half2float(h0));
    const __half l1 = __float2half(v1 - __half2float(h1));
    __half2 hh; hh.x = h0; hh.y = h1;
    __half2 ll; ll.x = l0; ll.y = l1;
    *reinterpret_cast<__half2*>(ph) = hh;
    *reinterpret_cast<__half2*>(pl) = ll;
}

// ------------------------------------------------------------------ smem map (dynamic)
static constexpr uint32_t TILE_BYTES = 128 * 128;         // 128 rows x 128B (64 halfs)
static constexpr uint32_t OFF_A0  = 0;
static constexpr uint32_t OFF_A1  = OFF_A0 + TILE_BYTES;  // 16384
static constexpr uint32_t OFF_B0  = OFF_A1 + TILE_BYTES;  // 32768
static constexpr uint32_t OFF_B1  = OFF_B0 + TILE_BYTES;  // 49152
static constexpr uint32_t OFF_SCL = OFF_B1 + TILE_BYTES;  // 65536
static constexpr uint32_t SMEM_BYTES = OFF_SCL + 512 + 16;

// ------------------------------------------------------------------ main GEMM + RK4 epilogue
// 2-pass split: [A_hi | A_lo] @ [B_hi | B_hi]  == exact (A_hi+A_lo) @ B_hi.
// Dropped h@R_lo term ~1e-4 relative — inside the 1e-3 budget.
// MODE 0: XKb = x@K + bias (KSEG=256).  MODE 1..4: RK4 stages (KSEG=512).
template <int MODE, int KSEG, bool LAST>
__global__ void __launch_bounds__(256, 2)
ctrnn_gemm(const float* __restrict__ sb, float* __restrict__ outp) {
    extern __shared__ char smem[];
    const uint32_t sbase = smem_u32(smem);
    const int tid  = threadIdx.x;
    const int lane = tid & 31;
    const int wid  = tid >> 5;
    const int warpM = (wid & 3) * 32;        // 4 warps along M
    const int warpN = (wid >> 2) * 64;       // 2 warps along N
    const int rowBase = blockIdx.x * 128;
    const int nBase   = blockIdx.y * 128;

    constexpr int CHPS = KSEG / 64;
    constexpr int NCH  = 2 * CHPS;           // 2-pass split

    const __half *Ah, *Al, *Bh;
    if constexpr (MODE == 0)      { Ah = g_Xh;  Al = g_Xl;  Bh = g_Kth; }
    else if constexpr (MODE == 1) { Ah = g_H0h; Al = g_H0l; Bh = g_Rth; }
    else if constexpr (MODE == 2) { Ah = g_HAh; Al = g_HAl; Bh = g_Rth; }
    else if constexpr (MODE == 3) { Ah = g_HBh; Al = g_HBl; Bh = g_Rth; }
    else                          { Ah = g_HAh; Al = g_HAl; Bh = g_Rth; }

    __half *nxh = nullptr, *nxl = nullptr;
    if constexpr (MODE == 1)               { nxh = g_HAh; nxl = g_HAl; }
    else if constexpr (MODE == 2)          { nxh = g_HBh; nxl = g_HBl; }
    else if constexpr (MODE == 3)          { nxh = g_HAh; nxl = g_HAl; }
    else if constexpr (MODE == 4 && !LAST) { nxh = g_H0h; nxl = g_H0l; }

    if (tid < 128)
        reinterpret_cast<float*>(smem + OFF_SCL)[tid] = sb[nBase + tid];

    const __half* Aseg[2] = {Ah, Al};

    // slot mapping for cp.async: 1024 slots per tile (128 rows x 8 col16)
    const int srow = tid >> 3;
    const int scol = tid & 7;

    auto load_chunk = [&](int c, int buf) {
        const int seg = c / CHPS;
        const int kof = (c % CHPS) * 64;
        const __half* As = Aseg[seg];
        const __half* Bs = Bh;
        const uint32_t aOff = buf ? OFF_A1 : OFF_A0;
        const uint32_t bOff = buf ? OFF_B1 : OFF_B0;
#pragma unroll
        for (int i = 0; i < 4; ++i) {
            const int r = srow + i * 32;
            uint32_t off = (uint32_t)(r * 128 + ((scol ^ (r & 7)) << 4));
            cp_async16(sbase + aOff + off,
                       As + (size_t)(rowBase + r) * KSEG + kof + scol * 8);
        }
#pragma unroll
        for (int i = 0; i < 4; ++i) {
            const int r = srow + i * 32;
            uint32_t off = (uint32_t)(r * 128 + ((scol ^ (r & 7)) << 4));
            cp_async16(sbase + bOff + off,
                       Bs + (size_t)(nBase + r) * KSEG + kof + scol * 8);
        }
        CP_COMMIT();
    };

    float acc[2][8][4];
#pragma unroll
    for (int mf = 0; mf < 2; ++mf)
#pragma unroll
        for (int nf = 0; nf < 8; ++nf)
#pragma unroll
            for (int i = 0; i < 4; ++i) acc[mf][nf][i] = 0.0f;

    // 2-stage pipeline: one barrier per chunk; L(c+1) overlaps MMA(c).
    load_chunk(0, 0);

    for (int c = 0; c < NCH; ++c) {
        CP_WAIT(0);
        __syncthreads();
        if (c + 1 < NCH) load_chunk(c + 1, (c + 1) & 1);

        const uint32_t aBase = sbase + ((c & 1) ? OFF_A1 : OFF_A0);
        const uint32_t bBase = sbase + ((c & 1) ? OFF_B1 : OFF_B0);
#pragma unroll
        for (int q = 0; q < 4; ++q) {
            uint32_t a[2][4];
#pragma unroll
            for (int mf = 0; mf < 2; ++mf) {
                const int row = warpM + mf * 16 + ((lane >> 3) & 1) * 8 + (lane & 7);
                const int c16 = q * 2 + (lane >> 4);
                const uint32_t addr = aBase + row * 128 + (((c16 ^ (row & 7)) & 7) << 4);
                ldsm_x4(addr, a[mf][0], a[mf][1], a[mf][2], a[mf][3]);
            }
#pragma unroll
            for (int g = 0; g < 4; ++g) {
                uint32_t b0, b1, b2, b3;
                const int row = warpN + g * 16 + ((lane >> 3) & 1) * 8 + (lane & 7);
                const int c16 = q * 2 + (lane >> 4);
                const uint32_t addr = bBase + row * 128 + (((c16 ^ (row & 7)) & 7) << 4);
                ldsm_x4(addr, b0, b1, b2, b3);
#pragma unroll
                for (int mf = 0; mf < 2; ++mf) {
                    mma16816(acc[mf][2 * g],     a[mf], b0, b2);
                    mma16816(acc[mf][2 * g + 1], a[mf], b1, b3);
                }
            }
        }
    }

    // ---------------- RK4 epilogue ----------------
    const float* scl = reinterpret_cast<const float*>(smem + OFF_SCL);

#pragma unroll
    for (int mf = 0; mf < 2; ++mf) {
#pragma unroll
        for (int nf = 0; nf < 8; ++nf) {
#pragma unroll
            for (int half_ = 0; half_ < 2; ++half_) {
                const int row = rowBase + warpM + mf * 16 + (lane >> 2) + half_ * 8;
                const int lc  = warpN + nf * 8 + (lane & 3) * 2;   // local col 0..127
                const int col = nBase + lc;
                const float c0 = acc[mf][nf][half_ * 2 + 0];
                const float c1 = acc[mf][nf][half_ * 2 + 1];
                const size_t eb = (size_t)row * UNITS + col;

                if constexpr (MODE == 0) {
                    float2 o;
                    o.x = c0 + scl[lc];
                    o.y = c1 + scl[lc + 1];
                    *reinterpret_cast<float2*>(g_XKb + eb) = o;
                } else {
                    const float2 xk = *reinterpret_cast<const float2*>(g_XKb + eb);
                    const __half2 ah = *reinterpret_cast<const __half2*>(Ah + eb);
                    const __half2 al = *reinterpret_cast<const __half2*>(Al + eb);
                    const float hs0 = __half2float(ah.x) + __half2float(al.x);
                    const float hs1 = __half2float(ah.y) + __half2float(al.y);
                    const float k0 = scl[lc]     * tanh_fast(c0 + xk.x) - hs0;
                    const float k1 = scl[lc + 1] * tanh_fast(c1 + xk.y) - hs1;

                    if constexpr (MODE == 1) {
                        hsplit2(nxh + eb, nxl + eb, hs0 + DT2 * k0, hs1 + DT2 * k1);
                        float2 sv; sv.x = hs0 + DT6 * k0; sv.y = hs1 + DT6 * k1;
                        *reinterpret_cast<float2*>(g_S + eb) = sv;
                    } else if constexpr (MODE == 2 || MODE == 3) {
                        const __half2 h0a = *reinterpret_cast<const __half2*>(g_H0h + eb);
                        const __half2 h0b = *reinterpret_cast<const __half2*>(g_H0l + eb);
                        const float h00 = __half2float(h0a.x) + __half2float(h0b.x);
                        const float h01 = __half2float(h0a.y) + __half2float(h0b.y);
                        const float2 s = *reinterpret_cast<const float2*>(g_S + eb);
                        constexpr float HC = (MODE == 2) ? DT2 : DT;
                        hsplit2(nxh + eb, nxl + eb, h00 + HC * k0, h01 + HC * k1);
                        float2 sn; sn.x = s.x + DT3 * k0; sn.y = s.y + DT3 * k1;
                        *reinterpret_cast<float2*>(g_S + eb) = sn;
                    } else {  // MODE 4
                        const float2 s = *reinterpret_cast<const float2*>(g_S + eb);
                        const float f0 = s.x + DT6 * k0;
                        const float f1 = s.y + DT6 * k1;
                        if constexpr (LAST) {
                            float2 o; o.x = f0; o.y = f1;
                            *reinterpret_cast<float2*>(outp + eb) = o;
                        } else {
                            hsplit2(nxh + eb, nxl + eb, f0, f1);
                        }
                    }
                }
            }
        }
    }
}

// ------------------------------------------------------------------ prep kernels
__global__ void split_kernel(const float* __restrict__ src,
                             __half* __restrict__ hi, __half* __restrict__ lo, int n4) {
    const int i = blockIdx.x * blockDim.x + threadIdx.x;
    if (i >= n4) return;
    const float4 v = reinterpret_cast<const float4*>(src)[i];
    hsplit2(hi + (size_t)i * 4,     lo + (size_t)i * 4,     v.x, v.y);
    hsplit2(hi + (size_t)i * 4 + 2, lo + (size_t)i * 4 + 2, v.z, v.w);
}

__global__ void trans_kernel(const float* __restrict__ W,
                             __half* __restrict__ Th, int K, int N) {
    const int idx = blockIdx.x * blockDim.x + threadIdx.x;
    if (idx >= K * N) return;
    const int k = idx / N, n = idx % N;
    Th[(size_t)n * K + k] = __float2half(W[idx]);
}

// ------------------------------------------------------------------ launch
extern "C" void kernel_launch(void* const* d_in, const int* in_sizes, int n_in,
                              void* d_out, int out_size) {
    const float* x     = (const float*)d_in[0];
    const float* h     = (const float*)d_in[1];
    const float* Km    = (const float*)d_in[2];
    const float* Rm    = (const float*)d_in[3];
    const float* bias  = (const float*)d_in[4];
    const float* scale = (const float*)d_in[5];
    float* out = (float*)d_out;

    cudaFuncSetAttribute(ctrnn_gemm<0, 256, false>, cudaFuncAttributeMaxDynamicSharedMemorySize, SMEM_BYTES);
    cudaFuncSetAttribute(ctrnn_gemm<1, 512, false>, cudaFuncAttributeMaxDynamicSharedMemorySize, SMEM_BYTES);
    cudaFuncSetAttribute(ctrnn_gemm<2, 512, false>, cudaFuncAttributeMaxDynamicSharedMemorySize, SMEM_BYTES);
    cudaFuncSetAttribute(ctrnn_gemm<3, 512, false>, cudaFuncAttributeMaxDynamicSharedMemorySize, SMEM_BYTES);
    cudaFuncSetAttribute(ctrnn_gemm<4, 512, false>, cudaFuncAttributeMaxDynamicSharedMemorySize, SMEM_BYTES);
    cudaFuncSetAttribute(ctrnn_gemm<4, 512, true>,  cudaFuncAttributeMaxDynamicSharedMemorySize, SMEM_BYTES);

    __half *h0h, *h0l, *xh, *xl, *rth, *kth;
    cudaGetSymbolAddress((void**)&h0h, g_H0h);
    cudaGetSymbolAddress((void**)&h0l, g_H0l);
    cudaGetSymbolAddress((void**)&xh,  g_Xh);
    cudaGetSymbolAddress((void**)&xl,  g_Xl);
    cudaGetSymbolAddress((void**)&rth, g_Rth);
    cudaGetSymbolAddress((void**)&kth, g_Kth);

    split_kernel<<<(BROWS * UNITS / 4) / 256, 256>>>(h, h0h, h0l, BROWS * UNITS / 4);
    split_kernel<<<(BROWS * DIN / 4) / 256, 256>>>(x, xh, xl, BROWS * DIN / 4);
    trans_kernel<<<(UNITS * UNITS) / 256, 256>>>(Rm, rth, UNITS, UNITS);
    trans_kernel<<<(DIN * UNITS) / 256, 256>>>(Km, kth, DIN, UNITS);

    const dim3 gg(BROWS / 128, UNITS / 128);
    ctrnn_gemm<0, 256, false><<<gg, 256, SMEM_BYTES>>>(bias, nullptr);

    for (int u = 0; u < 6; ++u) {
        ctrnn_gemm<1, 512, false><<<gg, 256, SMEM_BYTES>>>(scale, nullptr);
        ctrnn_gemm<2, 512, false><<<gg, 256, SMEM_BYTES>>>(scale, nullptr);
        ctrnn_gemm<3, 512, false><<<gg, 256, SMEM_BYTES>>>(scale, nullptr);
        if (u == 5) ctrnn_gemm<4, 512, true><<<gg, 256, SMEM_BYTES>>>(scale, out);
        else        ctrnn_gemm<4, 512, false><<<gg, 256, SMEM_BYTES>>>(scale, nullptr);
    }
}

// round 8
// speedup vs baseline: 1.3381x; 1.1179x over previous
#include <cuda_runtime.h>
#include <cuda_fp16.h>
#include <cstdint>
#include <cstddef>

#define BROWS 32768
#define DIN   256
#define UNITS 512

static constexpr float DT  = 1.0f / 6.0f;
static constexpr float DT2 = DT * 0.5f;
static constexpr float DT3 = DT / 3.0f;
static constexpr float DT6 = DT / 6.0f;

// ------------------------------------------------------------------ scratch
__device__ alignas(16) float  g_XKb[(size_t)BROWS * UNITS];
__device__ alignas(16) float  g_S  [(size_t)BROWS * UNITS];
__device__ alignas(16) __half g_H0h[(size_t)BROWS * UNITS];
__device__ alignas(16) __half g_H0l[(size_t)BROWS * UNITS];
__device__ alignas(16) __half g_HAh[(size_t)BROWS * UNITS];
__device__ alignas(16) __half g_HAl[(size_t)BROWS * UNITS];
__device__ alignas(16) __half g_HBh[(size_t)BROWS * UNITS];
__device__ alignas(16) __half g_HBl[(size_t)BROWS * UNITS];
__device__ alignas(16) __half g_Xh [(size_t)BROWS * DIN];
__device__ alignas(16) __half g_Xl [(size_t)BROWS * DIN];
__device__ alignas(16) __half g_Rth[UNITS * UNITS];
__device__ alignas(16) __half g_Kth[UNITS * DIN];

// ------------------------------------------------------------------ helpers
__device__ __forceinline__ uint32_t smem_u32(const void* p) {
    uint32_t a;
    asm("{ .reg .u64 t; cvta.to.shared.u64 t, %1; cvt.u32.u64 %0, t; }" : "=r"(a) : "l"(p));
    return a;
}

__device__ __forceinline__ void cp_async16(uint32_t saddr, const void* gaddr) {
    asm volatile("cp.async.cg.shared.global [%0], [%1], 16;" :: "r"(saddr), "l"(gaddr));
}
#define CP_COMMIT() asm volatile("cp.async.commit_group;" ::: "memory")
#define CP_WAIT(n)  asm volatile("cp.async.wait_group %0;" :: "n"(n) : "memory")

__device__ __forceinline__ void ldsm_x4(uint32_t addr, uint32_t& r0, uint32_t& r1,
                                        uint32_t& r2, uint32_t& r3) {
    asm volatile("ldmatrix.sync.aligned.m8n8.x4.shared.b16 {%0,%1,%2,%3}, [%4];"
                 : "=r"(r0), "=r"(r1), "=r"(r2), "=r"(r3) : "r"(addr));
}

__device__ __forceinline__ void mma16816(float* c, const uint32_t* a,
                                         uint32_t b0, uint32_t b1) {
    asm volatile("mma.sync.aligned.m16n8k16.row.col.f32.f16.f16.f32 "
                 "{%0,%1,%2,%3}, {%4,%5,%6,%7}, {%8,%9}, {%0,%1,%2,%3};"
                 : "+f"(c[0]), "+f"(c[1]), "+f"(c[2]), "+f"(c[3])
                 : "r"(a[0]), "r"(a[1]), "r"(a[2]), "r"(a[3]), "r"(b0), "r"(b1));
}

__device__ __forceinline__ float tanh_fast(float x) {
    const float e = __expf(2.0f * x);
    return 1.0f - 2.0f / (e + 1.0f);
}

__device__ __forceinline__ void hsplit2(__half* ph, __half* pl, float v0, float v1) {
    const __half h0 = __float2half(v0);
    const __half h1 = __float2half(v1);
    const __half l0 = __float2half(v0 - __half2float(h0));
    const __half l1 = __float2half(v1 - __half2float(h1));
    __half2 hh; hh.x = h0; hh.y = h1;
    __half2 ll; ll.x = l0; ll.y = l1;
    *reinterpret_cast<__half2*>(ph) = hh;
    *reinterpret_cast<__half2*>(pl) = ll;
}

// ------------------------------------------------------------------ smem map (dynamic)
static constexpr uint32_t TILE_BYTES = 128 * 128;         // 128 rows x 128B (64 halfs)
static constexpr uint32_t OFF_A0  = 0;
static constexpr uint32_t OFF_A1  = OFF_A0 + TILE_BYTES;  // 16384
static constexpr uint32_t OFF_B0  = OFF_A1 + TILE_BYTES;  // 32768
static constexpr uint32_t OFF_B1  = OFF_B0 + TILE_BYTES;  // 49152
static constexpr uint32_t OFF_SCL = OFF_B1 + TILE_BYTES;  // 65536
static constexpr uint32_t SMEM_BYTES = OFF_SCL + 512 + 16;

// ------------------------------------------------------------------ main GEMM + RK4 epilogue
// NPASS=2: [A_hi | A_lo] @ [B_hi | B_hi] (exact A @ B_hi)   — used for x@K (once)
// NPASS=1: A_hi @ B_hi (drops A_lo term, ~2e-4 rel/stage)   — used for stage GEMMs
// State storage stays hi+lo (full precision RK4 combination).
// Grid: blockIdx.x = N-block (fast-varying -> CTAs sharing A-rows are L2-concurrent),
//       blockIdx.y = M-block.
template <int MODE, int KSEG, int NPASS, bool LAST>
__global__ void __launch_bounds__(256, 2)
ctrnn_gemm(const float* __restrict__ sb, float* __restrict__ outp) {
    extern __shared__ char smem[];
    const uint32_t sbase = smem_u32(smem);
    const int tid  = threadIdx.x;
    const int lane = tid & 31;
    const int wid  = tid >> 5;
    const int warpM = (wid & 3) * 32;        // 4 warps along M
    const int warpN = (wid >> 2) * 64;       // 2 warps along N
    const int rowBase = blockIdx.y * 128;
    const int nBase   = blockIdx.x * 128;

    constexpr int CHPS = KSEG / 64;
    constexpr int NCH  = NPASS * CHPS;

    const __half *Ah, *Al, *Bh;
    if constexpr (MODE == 0)      { Ah = g_Xh;  Al = g_Xl;  Bh = g_Kth; }
    else if constexpr (MODE == 1) { Ah = g_H0h; Al = g_H0l; Bh = g_Rth; }
    else if constexpr (MODE == 2) { Ah = g_HAh; Al = g_HAl; Bh = g_Rth; }
    else if constexpr (MODE == 3) { Ah = g_HBh; Al = g_HBl; Bh = g_Rth; }
    else                          { Ah = g_HAh; Al = g_HAl; Bh = g_Rth; }

    __half *nxh = nullptr, *nxl = nullptr;
    if constexpr (MODE == 1)               { nxh = g_HAh; nxl = g_HAl; }
    else if constexpr (MODE == 2)          { nxh = g_HBh; nxl = g_HBl; }
    else if constexpr (MODE == 3)          { nxh = g_HAh; nxl = g_HAl; }
    else if constexpr (MODE == 4 && !LAST) { nxh = g_H0h; nxl = g_H0l; }

    if (tid < 128)
        reinterpret_cast<float*>(smem + OFF_SCL)[tid] = sb[nBase + tid];

    const __half* Aseg[2] = {Ah, (NPASS == 2) ? Al : Ah};

    // slot mapping for cp.async: 1024 slots per tile (128 rows x 8 col16)
    const int srow = tid >> 3;
    const int scol = tid & 7;

    auto load_chunk = [&](int c, int buf) {
        const int seg = c / CHPS;
        const int kof = (c % CHPS) * 64;
        const __half* As = Aseg[seg];
        const __half* Bs = Bh;
        const uint32_t aOff = buf ? OFF_A1 : OFF_A0;
        const uint32_t bOff = buf ? OFF_B1 : OFF_B0;
#pragma unroll
        for (int i = 0; i < 4; ++i) {
            const int r = srow + i * 32;
            uint32_t off = (uint32_t)(r * 128 + ((scol ^ (r & 7)) << 4));
            cp_async16(sbase + aOff + off,
                       As + (size_t)(rowBase + r) * KSEG + kof + scol * 8);
        }
#pragma unroll
        for (int i = 0; i < 4; ++i) {
            const int r = srow + i * 32;
            uint32_t off = (uint32_t)(r * 128 + ((scol ^ (r & 7)) << 4));
            cp_async16(sbase + bOff + off,
                       Bs + (size_t)(nBase + r) * KSEG + kof + scol * 8);
        }
        CP_COMMIT();
    };

    float acc[2][8][4];
#pragma unroll
    for (int mf = 0; mf < 2; ++mf)
#pragma unroll
        for (int nf = 0; nf < 8; ++nf)
#pragma unroll
            for (int i = 0; i < 4; ++i) acc[mf][nf][i] = 0.0f;

    // 2-stage pipeline: one barrier per chunk; L(c+1) overlaps MMA(c).
    load_chunk(0, 0);

    for (int c = 0; c < NCH; ++c) {
        CP_WAIT(0);
        __syncthreads();
        if (c + 1 < NCH) load_chunk(c + 1, (c + 1) & 1);

        const uint32_t aBase = sbase + ((c & 1) ? OFF_A1 : OFF_A0);
        const uint32_t bBase = sbase + ((c & 1) ? OFF_B1 : OFF_B0);
#pragma unroll
        for (int q = 0; q < 4; ++q) {
            uint32_t a[2][4];
#pragma unroll
            for (int mf = 0; mf < 2; ++mf) {
                const int row = warpM + mf * 16 + ((lane >> 3) & 1) * 8 + (lane & 7);
                const int c16 = q * 2 + (lane >> 4);
                const uint32_t addr = aBase + row * 128 + (((c16 ^ (row & 7)) & 7) << 4);
                ldsm_x4(addr, a[mf][0], a[mf][1], a[mf][2], a[mf][3]);
            }
#pragma unroll
            for (int g = 0; g < 4; ++g) {
                uint32_t b0, b1, b2, b3;
                const int row = warpN + g * 16 + ((lane >> 3) & 1) * 8 + (lane & 7);
                const int c16 = q * 2 + (lane >> 4);
                const uint32_t addr = bBase + row * 128 + (((c16 ^ (row & 7)) & 7) << 4);
                ldsm_x4(addr, b0, b1, b2, b3);
#pragma unroll
                for (int mf = 0; mf < 2; ++mf) {
                    mma16816(acc[mf][2 * g],     a[mf], b0, b2);
                    mma16816(acc[mf][2 * g + 1], a[mf], b1, b3);
                }
            }
        }
    }

    // ---------------- RK4 epilogue ----------------
    const float* scl = reinterpret_cast<const float*>(smem + OFF_SCL);

#pragma unroll
    for (int mf = 0; mf < 2; ++mf) {
#pragma unroll
        for (int nf = 0; nf < 8; ++nf) {
#pragma unroll
            for (int half_ = 0; half_ < 2; ++half_) {
                const int row = rowBase + warpM + mf * 16 + (lane >> 2) + half_ * 8;
                const int lc  = warpN + nf * 8 + (lane & 3) * 2;   // local col 0..127
                const int col = nBase + lc;
                const float c0 = acc[mf][nf][half_ * 2 + 0];
                const float c1 = acc[mf][nf][half_ * 2 + 1];
                const size_t eb = (size_t)row * UNITS + col;

                if constexpr (MODE == 0) {
                    float2 o;
                    o.x = c0 + scl[lc];
                    o.y = c1 + scl[lc + 1];
                    *reinterpret_cast<float2*>(g_XKb + eb) = o;
                } else {
                    const float2 xk = *reinterpret_cast<const float2*>(g_XKb + eb);
                    const __half2 ah = *reinterpret_cast<const __half2*>(Ah + eb);
                    const __half2 al = *reinterpret_cast<const __half2*>(Al + eb);
                    const float hs0 = __half2float(ah.x) + __half2float(al.x);
                    const float hs1 = __half2float(ah.y) + __half2float(al.y);
                    const float k0 = scl[lc]     * tanh_fast(c0 + xk.x) - hs0;
                    const float k1 = scl[lc + 1] * tanh_fast(c1 + xk.y) - hs1;

                    if constexpr (MODE == 1) {
                        hsplit2(nxh + eb, nxl + eb, hs0 + DT2 * k0, hs1 + DT2 * k1);
                        float2 sv; sv.x = hs0 + DT6 * k0; sv.y = hs1 + DT6 * k1;
                        *reinterpret_cast<float2*>(g_S + eb) = sv;
                    } else if constexpr (MODE == 2 || MODE == 3) {
                        const __half2 h0a = *reinterpret_cast<const __half2*>(g_H0h + eb);
                        const __half2 h0b = *reinterpret_cast<const __half2*>(g_H0l + eb);
                        const float h00 = __half2float(h0a.x) + __half2float(h0b.x);
                        const float h01 = __half2float(h0a.y) + __half2float(h0b.y);
                        const float2 s = *reinterpret_cast<const float2*>(g_S + eb);
                        constexpr float HC = (MODE == 2) ? DT2 : DT;
                        hsplit2(nxh + eb, nxl + eb, h00 + HC * k0, h01 + HC * k1);
                        float2 sn; sn.x = s.x + DT3 * k0; sn.y = s.y + DT3 * k1;
                        *reinterpret_cast<float2*>(g_S + eb) = sn;
                    } else {  // MODE 4
                        const float2 s = *reinterpret_cast<const float2*>(g_S + eb);
                        const float f0 = s.x + DT6 * k0;
                        const float f1 = s.y + DT6 * k1;
                        if constexpr (LAST) {
                            float2 o; o.x = f0; o.y = f1;
                            *reinterpret_cast<float2*>(outp + eb) = o;
                        } else {
                            hsplit2(nxh + eb, nxl + eb, f0, f1);
                        }
                    }
                }
            }
        }
    }
}

// ------------------------------------------------------------------ prep kernels
__global__ void split_kernel(const float* __restrict__ src,
                             __half* __restrict__ hi, __half* __restrict__ lo, int n4) {
    const int i = blockIdx.x * blockDim.x + threadIdx.x;
    if (i >= n4) return;
    const float4 v = reinterpret_cast<const float4*>(src)[i];
    hsplit2(hi + (size_t)i * 4,     lo + (size_t)i * 4,     v.x, v.y);
    hsplit2(hi + (size_t)i * 4 + 2, lo + (size_t)i * 4 + 2, v.z, v.w);
}

__global__ void trans_kernel(const float* __restrict__ W,
                             __half* __restrict__ Th, int K, int N) {
    const int idx = blockIdx.x * blockDim.x + threadIdx.x;
    if (idx >= K * N) return;
    const int k = idx / N, n = idx % N;
    Th[(size_t)n * K + k] = __float2half(W[idx]);
}

// ------------------------------------------------------------------ launch
extern "C" void kernel_launch(void* const* d_in, const int* in_sizes, int n_in,
                              void* d_out, int out_size) {
    const float* x     = (const float*)d_in[0];
    const float* h     = (const float*)d_in[1];
    const float* Km    = (const float*)d_in[2];
    const float* Rm    = (const float*)d_in[3];
    const float* bias  = (const float*)d_in[4];
    const float* scale = (const float*)d_in[5];
    float* out = (float*)d_out;

    cudaFuncSetAttribute(ctrnn_gemm<0, 256, 2, false>, cudaFuncAttributeMaxDynamicSharedMemorySize, SMEM_BYTES);
    cudaFuncSetAttribute(ctrnn_gemm<1, 512, 1, false>, cudaFuncAttributeMaxDynamicSharedMemorySize, SMEM_BYTES);
    cudaFuncSetAttribute(ctrnn_gemm<2, 512, 1, false>, cudaFuncAttributeMaxDynamicSharedMemorySize, SMEM_BYTES);
    cudaFuncSetAttribute(ctrnn_gemm<3, 512, 1, false>, cudaFuncAttributeMaxDynamicSharedMemorySize, SMEM_BYTES);
    cudaFuncSetAttribute(ctrnn_gemm<4, 512, 1, false>, cudaFuncAttributeMaxDynamicSharedMemorySize, SMEM_BYTES);
    cudaFuncSetAttribute(ctrnn_gemm<4, 512, 1, true>,  cudaFuncAttributeMaxDynamicSharedMemorySize, SMEM_BYTES);

    __half *h0h, *h0l, *xh, *xl, *rth, *kth;
    cudaGetSymbolAddress((void**)&h0h, g_H0h);
    cudaGetSymbolAddress((void**)&h0l, g_H0l);
    cudaGetSymbolAddress((void**)&xh,  g_Xh);
    cudaGetSymbolAddress((void**)&xl,  g_Xl);
    cudaGetSymbolAddress((void**)&rth, g_Rth);
    cudaGetSymbolAddress((void**)&kth, g_Kth);

    split_kernel<<<(BROWS * UNITS / 4) / 256, 256>>>(h, h0h, h0l, BROWS * UNITS / 4);
    split_kernel<<<(BROWS * DIN / 4) / 256, 256>>>(x, xh, xl, BROWS * DIN / 4);
    trans_kernel<<<(UNITS * UNITS) / 256, 256>>>(Rm, rth, UNITS, UNITS);
    trans_kernel<<<(DIN * UNITS) / 256, 256>>>(Km, kth, DIN, UNITS);

    // N-block fastest (x), M-block slow (y): CTAs sharing A-rows are L2-concurrent.
    const dim3 gg(UNITS / 128, BROWS / 128);
    ctrnn_gemm<0, 256, 2, false><<<gg, 256, SMEM_BYTES>>>(bias, nullptr);

    for (int u = 0; u < 6; ++u) {
        ctrnn_gemm<1, 512, 1, false><<<gg, 256, SMEM_BYTES>>>(scale, nullptr);
        ctrnn_gemm<2, 512, 1, false><<<gg, 256, SMEM_BYTES>>>(scale, nullptr);
        ctrnn_gemm<3, 512, 1, false><<<gg, 256, SMEM_BYTES>>>(scale, nullptr);
        if (u == 5) ctrnn_gemm<4, 512, 1, true><<<gg, 256, SMEM_BYTES>>>(scale, out);
        else        ctrnn_gemm<4, 512, 1, false><<<gg, 256, SMEM_BYTES>>>(scale, nullptr);
    }
}